// round 4
// baseline (speedup 1.0000x reference)
#include <cuda_runtime.h>

#define Hdim 1024
#define Wdim 1024
#define HWdim (Hdim * Wdim)
#define TS 32
#define NT 256

__device__ __forceinline__ float sigmoidf_(float y) {
    return 1.0f / (1.0f + __expf(-y));
}

__global__ __launch_bounds__(NT, 4) void unet_fused_kernel(
    const float* __restrict__ x,  const float* __restrict__ x2,
    const float* __restrict__ w1a, const float* __restrict__ b1a,
    const float* __restrict__ w2a, const float* __restrict__ b2a,
    const float* __restrict__ w3a, const float* __restrict__ b3a,
    const float* __restrict__ w1b, const float* __restrict__ b1b,
    const float* __restrict__ w2b, const float* __restrict__ b2b,
    const float* __restrict__ w3b, const float* __restrict__ b3b,
    const float* __restrict__ lw1, const float* __restrict__ lb1,
    const float* __restrict__ lw2, const float* __restrict__ lb2,
    float* __restrict__ outf, float* __restrict__ den1, float* __restrict__ den2)
{
    __shared__ float s_x[3][38][38];   // input tile, 3-halo
    __shared__ float s_c4[36][36];     // conv1 out, 2-halo
    __shared__ float s_c5[34][34];     // conv2 out, 1-halo
    __shared__ float s_w[108];         // w1(27) | w2(36) | w3(45)
    __shared__ float s_b[3];
    __shared__ float s_M[12];          // folded 6->2 matrix
    __shared__ float s_B2[2];

    const int tid = threadIdx.x;
    const int h0  = blockIdx.y * TS;
    const int w0  = blockIdx.x * TS;

    // Fold MLP (no inner nonlinearity): M = lw2@lw1, B = lw2@lb1 + lb2.
    // warp 0 only; overlaps the first tile load done by other warps.
    if (tid < 12) {
        int o = tid / 6, c = tid % 6;
        float acc = 0.0f;
        #pragma unroll 8
        for (int k = 0; k < 128; k++)
            acc += __ldg(&lw2[o * 128 + k]) * __ldg(&lw1[k * 6 + c]);
        s_M[tid] = acc;
    } else if (tid < 14) {
        int o = tid - 12;
        float acc = __ldg(&lb2[o]);
        #pragma unroll 8
        for (int k = 0; k < 128; k++)
            acc += __ldg(&lw2[o * 128 + k]) * __ldg(&lb1[k]);
        s_B2[o] = acc;
    }

    #pragma unroll 1
    for (int e = 0; e < 2; e++) {
        const float* X   = e ? x2  : x;
        const float* W1  = e ? w1b : w1a;
        const float* W2  = e ? w2b : w2a;
        const float* W3  = e ? w3b : w3a;
        const float* B1  = e ? b1b : b1a;
        const float* Bc2 = e ? b2b : b2a;
        const float* B3  = e ? b3b : b3a;
        float* den = e ? den2 : den1;

        __syncthreads();  // protect smem reuse across encoders

        // ---- load weights ----
        if (tid < 108) {
            float v;
            if (tid < 27)      v = __ldg(&W1[tid]);
            else if (tid < 63) v = __ldg(&W2[tid - 27]);
            else               v = __ldg(&W3[tid - 63]);
            s_w[tid] = v;
        }
        if (tid == 120) s_b[0] = __ldg(&B1[0]);
        if (tid == 121) s_b[1] = __ldg(&Bc2[0]);
        if (tid == 122) s_b[2] = __ldg(&B3[0]);

        // ---- load input tile (3 ch, 3-halo, zero padded) ----
        #pragma unroll 1
        for (int c = 0; c < 3; c++) {
            #pragma unroll 1
            for (int idx = tid; idx < 38 * 38; idx += NT) {
                int r = idx / 38;
                int q = idx - r * 38;
                int gh = h0 - 3 + r, gw = w0 - 3 + q;
                float v = 0.0f;
                if ((unsigned)gh < (unsigned)Hdim && (unsigned)gw < (unsigned)Wdim)
                    v = __ldg(&X[c * HWdim + gh * Wdim + gw]);
                s_x[c][r][q] = v;
            }
        }
        __syncthreads();

        // ---- conv1: 3ch -> c4 over 36x36. Outside-image positions must
        // be 0 (reference zero-pads the concatenated tensor). ----
        #pragma unroll 1
        for (int idx = tid; idx < 36 * 36; idx += NT) {
            int j = idx / 36, i = idx - (idx / 36) * 36;
            float acc = s_b[0];
            #pragma unroll
            for (int c = 0; c < 3; c++)
                #pragma unroll
                for (int kh = 0; kh < 3; kh++)
                    #pragma unroll
                    for (int kw = 0; kw < 3; kw++)
                        acc += s_w[c * 9 + kh * 3 + kw] * s_x[c][j + kh][i + kw];
            int gh = h0 + j - 2, gw = w0 + i - 2;
            bool in_img = (unsigned)gh < (unsigned)Hdim && (unsigned)gw < (unsigned)Wdim;
            s_c4[j][i] = in_img ? sigmoidf_(acc) : 0.0f;
        }
        __syncthreads();

        // ---- conv2: [x(3), c4] -> c5 over 34x34 ----
        #pragma unroll 1
        for (int idx = tid; idx < 34 * 34; idx += NT) {
            int j = idx / 34, i = idx - (idx / 34) * 34;
            float acc = s_b[1];
            #pragma unroll
            for (int c = 0; c < 3; c++)
                #pragma unroll
                for (int kh = 0; kh < 3; kh++)
                    #pragma unroll
                    for (int kw = 0; kw < 3; kw++)
                        acc += s_w[27 + c * 9 + kh * 3 + kw] * s_x[c][j + 1 + kh][i + 1 + kw];
            #pragma unroll
            for (int kh = 0; kh < 3; kh++)
                #pragma unroll
                for (int kw = 0; kw < 3; kw++)
                    acc += s_w[54 + kh * 3 + kw] * s_c4[j + kh][i + kw];
            int gh = h0 + j - 1, gw = w0 + i - 1;
            bool in_img = (unsigned)gh < (unsigned)Hdim && (unsigned)gw < (unsigned)Wdim;
            s_c5[j][i] = in_img ? sigmoidf_(acc) : 0.0f;
        }
        __syncthreads();

        // ---- conv3: [x(3), c4, c5] -> c6 + outputs, over 32x32 ----
        #pragma unroll 1
        for (int k = 0; k < (TS * TS) / NT; k++) {
            int p = tid + k * NT;
            int j = p >> 5, i = p & 31;
            float acc = s_b[2];
            #pragma unroll
            for (int c = 0; c < 3; c++)
                #pragma unroll
                for (int kh = 0; kh < 3; kh++)
                    #pragma unroll
                    for (int kw = 0; kw < 3; kw++)
                        acc += s_w[63 + c * 9 + kh * 3 + kw] * s_x[c][j + 2 + kh][i + 2 + kw];
            #pragma unroll
            for (int kh = 0; kh < 3; kh++)
                #pragma unroll
                for (int kw = 0; kw < 3; kw++)
                    acc += s_w[90 + kh * 3 + kw] * s_c4[j + 1 + kh][i + 1 + kw];
            #pragma unroll
            for (int kh = 0; kh < 3; kh++)
                #pragma unroll
                for (int kw = 0; kw < 3; kw++)
                    acc += s_w[99 + kh * 3 + kw] * s_c5[j + kh][i + kw];
            float f5 = sigmoidf_(acc);

            float f0 = s_x[0][j + 3][i + 3];
            float f1 = s_x[1][j + 3][i + 3];
            float f2 = s_x[2][j + 3][i + 3];
            float f3 = s_c4[j + 2][i + 2];
            float f4 = s_c5[j + 1][i + 1];

            int pix = (h0 + j) * Wdim + (w0 + i);
            float2* dp = (float2*)(den + (size_t)pix * 6);
            dp[0] = make_float2(f0, f1);
            dp[1] = make_float2(f2, f3);
            dp[2] = make_float2(f4, f5);

            // out = (B + M*fa) - M*fb, accumulated incrementally:
            float m0 = s_M[0]*f0 + s_M[1]*f1 + s_M[2]*f2
                     + s_M[3]*f3 + s_M[4]*f4 + s_M[5]*f5;
            float m1 = s_M[6]*f0 + s_M[7]*f1 + s_M[8]*f2
                     + s_M[9]*f3 + s_M[10]*f4 + s_M[11]*f5;
            float2* op = (float2*)outf + pix;
            if (e == 0) {
                *op = make_float2(s_B2[0] + m0, s_B2[1] + m1);
            } else {
                float2 prev = *op;  // written by this same thread in e=0
                *op = make_float2(prev.x - m0, prev.y - m1);
            }
        }
    }
}

extern "C" void kernel_launch(void* const* d_in, const int* in_sizes, int n_in,
                              void* d_out, int out_size) {
    const float* x   = (const float*)d_in[0];
    const float* x2  = (const float*)d_in[1];
    const float* w1a = (const float*)d_in[2];
    const float* b1a = (const float*)d_in[3];
    const float* w2a = (const float*)d_in[4];
    const float* b2a = (const float*)d_in[5];
    const float* w3a = (const float*)d_in[6];
    const float* b3a = (const float*)d_in[7];
    const float* w1b = (const float*)d_in[8];
    const float* b1b = (const float*)d_in[9];
    const float* w2b = (const float*)d_in[10];
    const float* b2b = (const float*)d_in[11];
    const float* w3b = (const float*)d_in[12];
    const float* b3b = (const float*)d_in[13];
    const float* lw1 = (const float*)d_in[14];
    const float* lb1 = (const float*)d_in[15];
    const float* lw2 = (const float*)d_in[16];
    const float* lb2 = (const float*)d_in[17];

    float* outf = (float*)d_out;                       // [HW, 2]
    float* den1 = (float*)d_out + (size_t)2 * HWdim;   // [H, W, 6]
    float* den2 = (float*)d_out + (size_t)8 * HWdim;   // [H, W, 6]

    dim3 grid(Wdim / TS, Hdim / TS);
    unet_fused_kernel<<<grid, NT>>>(
        x, x2, w1a, b1a, w2a, b2a, w3a, b3a,
        w1b, b1b, w2b, b2b, w3b, b3b,
        lw1, lb1, lw2, lb2,
        outf, den1, den2);
}

// round 5
// speedup vs baseline: 1.3848x; 1.3848x over previous
#include <cuda_runtime.h>

#define Hdim 1024
#define Wdim 1024
#define HWdim (Hdim * Wdim)
#define TS 32
#define NT 256

// smem layout in floats
#define OFF_X   0        // [2][3][38][38]: e*4332 + c*1444 + r*38 + q
#define OFF_C4  8664     // [2][36][36]:    e*1296 + j*36 + i
#define OFF_C5  11256    // [2][34][34]:    e*1156 + j*34 + i
#define OFF_OUT 13568    // [1024][2]
#define OFF_W   15616    // [2][108]
#define OFF_B   15832    // [2][3]
#define OFF_M   15838    // [12]
#define OFF_B2  15850    // [2]
#define SMEM_FLOATS 15852
#define SMEM_BYTES (SMEM_FLOATS * 4)

__device__ __forceinline__ float sigmoidf_(float y) {
    return 1.0f / (1.0f + __expf(-y));
}

__global__ __launch_bounds__(NT, 2) void unet_fused_kernel(
    const float* __restrict__ x,  const float* __restrict__ x2,
    const float* __restrict__ w1a, const float* __restrict__ b1a,
    const float* __restrict__ w2a, const float* __restrict__ b2a,
    const float* __restrict__ w3a, const float* __restrict__ b3a,
    const float* __restrict__ w1b, const float* __restrict__ b1b,
    const float* __restrict__ w2b, const float* __restrict__ b2b,
    const float* __restrict__ w3b, const float* __restrict__ b3b,
    const float* __restrict__ lw1, const float* __restrict__ lb1,
    const float* __restrict__ lw2, const float* __restrict__ lb2,
    float* __restrict__ outf, float* __restrict__ den1, float* __restrict__ den2)
{
    extern __shared__ float sm[];
    const int tid  = threadIdx.x;
    const int half = tid >> 7;        // 0 = encoder a, 1 = encoder b
    const int t    = tid & 127;
    const int h0   = blockIdx.y * TS;
    const int w0   = blockIdx.x * TS;

    // ---- fold MLP (no inner nonlinearity): M = lw2@lw1, B = lw2@lb1+lb2 ----
    if (tid < 12) {
        int o = tid / 6, c = tid % 6;
        float acc = 0.0f;
        #pragma unroll 8
        for (int k = 0; k < 128; k++)
            acc += __ldg(&lw2[o * 128 + k]) * __ldg(&lw1[k * 6 + c]);
        sm[OFF_M + tid] = acc;
    } else if (tid < 14) {
        int o = tid - 12;
        float acc = __ldg(&lb2[o]);
        #pragma unroll 8
        for (int k = 0; k < 128; k++)
            acc += __ldg(&lw2[o * 128 + k]) * __ldg(&lb1[k]);
        sm[OFF_B2 + o] = acc;
    }

    // ---- weights -> smem (threads 16..231), biases (232..237) ----
    if (tid >= 16 && tid < 16 + 216) {
        int wt = tid - 16;
        int e  = wt / 108;
        int k  = wt - e * 108;
        const float* src;
        int off;
        if (k < 27)      { src = e ? w1b : w1a; off = k; }
        else if (k < 63) { src = e ? w2b : w2a; off = k - 27; }
        else             { src = e ? w3b : w3a; off = k - 63; }
        sm[OFF_W + wt] = __ldg(&src[off]);
    }
    if (tid == 232) sm[OFF_B + 0] = __ldg(&b1a[0]);
    if (tid == 233) sm[OFF_B + 1] = __ldg(&b2a[0]);
    if (tid == 234) sm[OFF_B + 2] = __ldg(&b3a[0]);
    if (tid == 235) sm[OFF_B + 3] = __ldg(&b1b[0]);
    if (tid == 236) sm[OFF_B + 4] = __ldg(&b2b[0]);
    if (tid == 237) sm[OFF_B + 5] = __ldg(&b3b[0]);

    // ---- load input tile for this half's encoder (3ch, 3-halo, zero-pad) ----
    {
        const float* X = half ? x2 : x;
        float* dst = sm + OFF_X + half * 4332;
        #pragma unroll 1
        for (int idx = t; idx < 3 * 1444; idx += 128) {
            int c   = idx / 1444;
            int rem = idx - c * 1444;
            int r   = rem / 38;
            int q   = rem - r * 38;
            int gh = h0 - 3 + r, gw = w0 - 3 + q;
            float v = 0.0f;
            if ((unsigned)gh < (unsigned)Hdim && (unsigned)gw < (unsigned)Wdim)
                v = __ldg(&X[c * HWdim + gh * Wdim + gw]);
            dst[idx] = v;
        }
    }
    __syncthreads();

    const float* xe  = sm + OFF_X  + half * 4332;
    float*       c4e = sm + OFF_C4 + half * 1296;
    float*       c5e = sm + OFF_C5 + half * 1156;

    // ================= conv1: 3ch -> c4 over 36x36 =================
    // Outside-image positions must be 0 (reference zero-pads the
    // concatenated tensor, so the conv channels are 0 outside the image).
    {
        float w[27];
        #pragma unroll
        for (int k = 0; k < 27; k++) w[k] = sm[OFF_W + half * 108 + k];
        const float b = sm[OFF_B + half * 3 + 0];

        #pragma unroll 1
        for (int idx = t; idx < 36 * 36; idx += 128) {
            int j = idx / 36, i = idx - (idx / 36) * 36;
            float ac[3];
            #pragma unroll
            for (int c = 0; c < 3; c++) {
                const float* p = xe + c * 1444 + j * 38 + i;
                float a = 0.0f;
                #pragma unroll
                for (int kh = 0; kh < 3; kh++)
                    #pragma unroll
                    for (int kw = 0; kw < 3; kw++)
                        a += w[c * 9 + kh * 3 + kw] * p[kh * 38 + kw];
                ac[c] = a;
            }
            float acc = b + ((ac[0] + ac[1]) + ac[2]);
            int gh = h0 + j - 2, gw = w0 + i - 2;
            bool in_img = (unsigned)gh < (unsigned)Hdim && (unsigned)gw < (unsigned)Wdim;
            c4e[idx] = in_img ? sigmoidf_(acc) : 0.0f;
        }
    }
    __syncthreads();

    // ================= conv2: [x(3), c4] -> c5 over 34x34 =================
    {
        float w[36];
        #pragma unroll
        for (int k = 0; k < 36; k++) w[k] = sm[OFF_W + half * 108 + 27 + k];
        const float b = sm[OFF_B + half * 3 + 1];

        #pragma unroll 1
        for (int idx = t; idx < 34 * 34; idx += 128) {
            int j = idx / 34, i = idx - (idx / 34) * 34;
            float ac[4];
            #pragma unroll
            for (int c = 0; c < 3; c++) {
                const float* p = xe + c * 1444 + (j + 1) * 38 + (i + 1);
                float a = 0.0f;
                #pragma unroll
                for (int kh = 0; kh < 3; kh++)
                    #pragma unroll
                    for (int kw = 0; kw < 3; kw++)
                        a += w[c * 9 + kh * 3 + kw] * p[kh * 38 + kw];
                ac[c] = a;
            }
            {
                const float* p = c4e + j * 36 + i;
                float a = 0.0f;
                #pragma unroll
                for (int kh = 0; kh < 3; kh++)
                    #pragma unroll
                    for (int kw = 0; kw < 3; kw++)
                        a += w[27 + kh * 3 + kw] * p[kh * 36 + kw];
                ac[3] = a;
            }
            float acc = b + ((ac[0] + ac[1]) + (ac[2] + ac[3]));
            int gh = h0 + j - 1, gw = w0 + i - 1;
            bool in_img = (unsigned)gh < (unsigned)Hdim && (unsigned)gw < (unsigned)Wdim;
            c5e[idx] = in_img ? sigmoidf_(acc) : 0.0f;
        }
    }
    __syncthreads();

    // ========= conv3: [x,c4,c5] -> c6 + den + outfeature, 32x32 =========
    {
        float w[45];
        #pragma unroll
        for (int k = 0; k < 45; k++) w[k] = sm[OFF_W + half * 108 + 63 + k];
        const float b = sm[OFF_B + half * 3 + 2];
        float M[12], B2[2];
        #pragma unroll
        for (int k = 0; k < 12; k++) M[k] = sm[OFF_M + k];
        B2[0] = sm[OFF_B2 + 0];
        B2[1] = sm[OFF_B2 + 1];
        float* den = half ? den2 : den1;

        float mb0[8], mb1[8];  // b-half: M·fb stash across the sync

        #pragma unroll
        for (int k = 0; k < 8; k++) {
            int idx = t + k * 128;       // 1024 items, 8 per thread exactly
            int j = idx >> 5, i = idx & 31;

            float ac[5];
            #pragma unroll
            for (int c = 0; c < 3; c++) {
                const float* p = xe + c * 1444 + (j + 2) * 38 + (i + 2);
                float a = 0.0f;
                #pragma unroll
                for (int kh = 0; kh < 3; kh++)
                    #pragma unroll
                    for (int kw = 0; kw < 3; kw++)
                        a += w[c * 9 + kh * 3 + kw] * p[kh * 38 + kw];
                ac[c] = a;
            }
            {
                const float* p = c4e + (j + 1) * 36 + (i + 1);
                float a = 0.0f;
                #pragma unroll
                for (int kh = 0; kh < 3; kh++)
                    #pragma unroll
                    for (int kw = 0; kw < 3; kw++)
                        a += w[27 + kh * 3 + kw] * p[kh * 36 + kw];
                ac[3] = a;
            }
            {
                const float* p = c5e + j * 34 + i;
                float a = 0.0f;
                #pragma unroll
                for (int kh = 0; kh < 3; kh++)
                    #pragma unroll
                    for (int kw = 0; kw < 3; kw++)
                        a += w[36 + kh * 3 + kw] * p[kh * 34 + kw];
                ac[4] = a;
            }
            float f5 = sigmoidf_(b + ((ac[0] + ac[1]) + (ac[2] + ac[3]) + ac[4]));

            float f0 = xe[0 * 1444 + (j + 3) * 38 + (i + 3)];
            float f1 = xe[1 * 1444 + (j + 3) * 38 + (i + 3)];
            float f2 = xe[2 * 1444 + (j + 3) * 38 + (i + 3)];
            float f3 = c4e[(j + 2) * 36 + (i + 2)];
            float f4 = c5e[(j + 1) * 34 + (i + 1)];

            int pix = (h0 + j) * Wdim + (w0 + i);
            float2* dp = (float2*)(den + (size_t)pix * 6);
            dp[0] = make_float2(f0, f1);
            dp[1] = make_float2(f2, f3);
            dp[2] = make_float2(f4, f5);

            float m0 = M[0]*f0 + M[1]*f1 + M[2]*f2 + M[3]*f3 + M[4]*f4 + M[5]*f5;
            float m1 = M[6]*f0 + M[7]*f1 + M[8]*f2 + M[9]*f3 + M[10]*f4 + M[11]*f5;

            if (half == 0) {
                *(float2*)(sm + OFF_OUT + idx * 2) = make_float2(B2[0] + m0, B2[1] + m1);
            } else {
                mb0[k] = m0;
                mb1[k] = m1;
            }
        }
        __syncthreads();

        if (half == 1) {
            #pragma unroll
            for (int k = 0; k < 8; k++) {
                int idx = t + k * 128;
                int j = idx >> 5, i = idx & 31;
                float2 pa = *(float2*)(sm + OFF_OUT + idx * 2);
                int pix = (h0 + j) * Wdim + (w0 + i);
                ((float2*)outf)[pix] = make_float2(pa.x - mb0[k], pa.y - mb1[k]);
            }
        }
    }
}

extern "C" void kernel_launch(void* const* d_in, const int* in_sizes, int n_in,
                              void* d_out, int out_size) {
    const float* x   = (const float*)d_in[0];
    const float* x2  = (const float*)d_in[1];
    const float* w1a = (const float*)d_in[2];
    const float* b1a = (const float*)d_in[3];
    const float* w2a = (const float*)d_in[4];
    const float* b2a = (const float*)d_in[5];
    const float* w3a = (const float*)d_in[6];
    const float* b3a = (const float*)d_in[7];
    const float* w1b = (const float*)d_in[8];
    const float* b1b = (const float*)d_in[9];
    const float* w2b = (const float*)d_in[10];
    const float* b2b = (const float*)d_in[11];
    const float* w3b = (const float*)d_in[12];
    const float* b3b = (const float*)d_in[13];
    const float* lw1 = (const float*)d_in[14];
    const float* lb1 = (const float*)d_in[15];
    const float* lw2 = (const float*)d_in[16];
    const float* lb2 = (const float*)d_in[17];

    float* outf = (float*)d_out;                       // [HW, 2]
    float* den1 = (float*)d_out + (size_t)2 * HWdim;   // [H, W, 6]
    float* den2 = (float*)d_out + (size_t)8 * HWdim;   // [H, W, 6]

    cudaFuncSetAttribute(unet_fused_kernel,
                         cudaFuncAttributeMaxDynamicSharedMemorySize, SMEM_BYTES);

    dim3 grid(Wdim / TS, Hdim / TS);
    unet_fused_kernel<<<grid, NT, SMEM_BYTES>>>(
        x, x2, w1a, b1a, w2a, b2a, w3a, b3a,
        w1b, b1b, w2b, b2b, w3b, b3b,
        lw1, lb1, lw2, lb2,
        outf, den1, den2);
}

// round 6
// speedup vs baseline: 1.5793x; 1.1405x over previous
#include <cuda_runtime.h>

#define Hdim 1024
#define Wdim 1024
#define HWdim (Hdim * Wdim)
#define TS 32
#define NT 256

__device__ __forceinline__ float sigmoidf_(float y) {
    return 1.0f / (1.0f + __expf(-y));
}

__global__ __launch_bounds__(NT, 3) void unet_fused_kernel(
    const float* __restrict__ x,  const float* __restrict__ x2,
    const float* __restrict__ w1a, const float* __restrict__ b1a,
    const float* __restrict__ w2a, const float* __restrict__ b2a,
    const float* __restrict__ w3a, const float* __restrict__ b3a,
    const float* __restrict__ w1b, const float* __restrict__ b1b,
    const float* __restrict__ w2b, const float* __restrict__ b2b,
    const float* __restrict__ w3b, const float* __restrict__ b3b,
    const float* __restrict__ lw1, const float* __restrict__ lb1,
    const float* __restrict__ lw2, const float* __restrict__ lb2,
    float* __restrict__ outf, float* __restrict__ den1, float* __restrict__ den2)
{
    __shared__ float s_x[3 * 38 * 38];
    __shared__ float s_c4[36 * 36];
    __shared__ float s_c5[34 * 34];
    __shared__ float s_w[108];
    __shared__ float s_b[3];
    __shared__ float s_M[12];
    __shared__ float s_B2[2];

    const int tid = threadIdx.x;
    const int h0  = blockIdx.y * TS;
    const int w0  = blockIdx.x * TS;

    // ---- fold MLP (no inner nonlinearity): M = lw2@lw1, B = lw2@lb1+lb2 ----
    if (tid < 12) {
        int o = tid / 6, c = tid % 6;
        float acc = 0.0f;
        #pragma unroll 8
        for (int k = 0; k < 128; k++)
            acc += __ldg(&lw2[o * 128 + k]) * __ldg(&lw1[k * 6 + c]);
        s_M[tid] = acc;
    } else if (tid < 14) {
        int o = tid - 12;
        float acc = __ldg(&lb2[o]);
        #pragma unroll 8
        for (int k = 0; k < 128; k++)
            acc += __ldg(&lw2[o * 128 + k]) * __ldg(&lb1[k]);
        s_B2[o] = acc;
    }

    #pragma unroll 1
    for (int e = 0; e < 2; e++) {
        const float* X   = e ? x2  : x;
        const float* W1  = e ? w1b : w1a;
        const float* W2  = e ? w2b : w2a;
        const float* W3  = e ? w3b : w3a;
        const float* B1  = e ? b1b : b1a;
        const float* Bc2 = e ? b2b : b2a;
        const float* B3  = e ? b3b : b3a;
        float* den = e ? den2 : den1;

        __syncthreads();  // protect smem reuse across encoders

        // ---- load weights + biases ----
        if (tid < 108) {
            float v;
            if (tid < 27)      v = __ldg(&W1[tid]);
            else if (tid < 63) v = __ldg(&W2[tid - 27]);
            else               v = __ldg(&W3[tid - 63]);
            s_w[tid] = v;
        }
        if (tid == 120) s_b[0] = __ldg(&B1[0]);
        if (tid == 121) s_b[1] = __ldg(&Bc2[0]);
        if (tid == 122) s_b[2] = __ldg(&B3[0]);

        // ---- load input tile (3 ch, 3-halo, zero padded) ----
        #pragma unroll 1
        for (int c = 0; c < 3; c++) {
            #pragma unroll 1
            for (int idx = tid; idx < 38 * 38; idx += NT) {
                int r = idx / 38;
                int q = idx - r * 38;
                int gh = h0 - 3 + r, gw = w0 - 3 + q;
                float v = 0.0f;
                if ((unsigned)gh < (unsigned)Hdim && (unsigned)gw < (unsigned)Wdim)
                    v = __ldg(&X[c * HWdim + gh * Wdim + gw]);
                s_x[c * 1444 + idx] = v;
            }
        }
        __syncthreads();

        // ============ conv1: 3ch -> c4, 36x36, 2-row blocked ============
        // Outside-image positions must be 0 (reference zero-pads the
        // concatenated tensor).
        {
            float w[27];
            #pragma unroll
            for (int k = 0; k < 27; k++) w[k] = s_w[k];
            const float bia = s_b[0];

            #pragma unroll 1
            for (int item = tid; item < 18 * 36; item += NT) {
                int jp = item / 36;
                int i  = item - jp * 36;
                int j  = jp * 2;
                float a0 = 0, a1 = 0, a2 = 0;   // out row j, split per channel
                float c0 = 0, c1 = 0, c2 = 0;   // out row j+1
                #pragma unroll
                for (int c = 0; c < 3; c++) {
                    const float* p = s_x + c * 1444 + j * 38 + i;
                    float r00 = p[0],   r01 = p[1],   r02 = p[2];
                    float r10 = p[38],  r11 = p[39],  r12 = p[40];
                    float r20 = p[76],  r21 = p[77],  r22 = p[78];
                    float r30 = p[114], r31 = p[115], r32 = p[116];
                    float ta = w[c*9+0]*r00 + w[c*9+1]*r01 + w[c*9+2]*r02
                             + w[c*9+3]*r10 + w[c*9+4]*r11 + w[c*9+5]*r12
                             + w[c*9+6]*r20 + w[c*9+7]*r21 + w[c*9+8]*r22;
                    float tb = w[c*9+0]*r10 + w[c*9+1]*r11 + w[c*9+2]*r12
                             + w[c*9+3]*r20 + w[c*9+4]*r21 + w[c*9+5]*r22
                             + w[c*9+6]*r30 + w[c*9+7]*r31 + w[c*9+8]*r32;
                    if (c == 0) { a0 = ta; c0 = tb; }
                    else if (c == 1) { a1 = ta; c1 = tb; }
                    else { a2 = ta; c2 = tb; }
                }
                int gw = w0 + i - 2;
                bool wi = (unsigned)gw < (unsigned)Wdim;
                int gh = h0 + j - 2;
                bool i0 = wi && (unsigned)gh < (unsigned)Hdim;
                bool i1 = wi && (unsigned)(gh + 1) < (unsigned)Hdim;
                s_c4[j * 36 + i]       = i0 ? sigmoidf_(bia + (a0 + a1) + a2) : 0.0f;
                s_c4[(j + 1) * 36 + i] = i1 ? sigmoidf_(bia + (c0 + c1) + c2) : 0.0f;
            }
        }
        __syncthreads();

        // ============ conv2: [x,c4] -> c5, 34x34, 2-row blocked ============
        {
            float w[36];
            #pragma unroll
            for (int k = 0; k < 36; k++) w[k] = s_w[27 + k];
            const float bia = s_b[1];

            #pragma unroll 1
            for (int item = tid; item < 17 * 34; item += NT) {
                int jp = item / 34;
                int i  = item - jp * 34;
                int j  = jp * 2;
                float a0 = 0, a1 = 0, a2 = 0, a3 = 0;
                float c0 = 0, c1 = 0, c2 = 0, c3 = 0;
                #pragma unroll
                for (int c = 0; c < 3; c++) {
                    const float* p = s_x + c * 1444 + (j + 1) * 38 + (i + 1);
                    float r00 = p[0],   r01 = p[1],   r02 = p[2];
                    float r10 = p[38],  r11 = p[39],  r12 = p[40];
                    float r20 = p[76],  r21 = p[77],  r22 = p[78];
                    float r30 = p[114], r31 = p[115], r32 = p[116];
                    float ta = w[c*9+0]*r00 + w[c*9+1]*r01 + w[c*9+2]*r02
                             + w[c*9+3]*r10 + w[c*9+4]*r11 + w[c*9+5]*r12
                             + w[c*9+6]*r20 + w[c*9+7]*r21 + w[c*9+8]*r22;
                    float tb = w[c*9+0]*r10 + w[c*9+1]*r11 + w[c*9+2]*r12
                             + w[c*9+3]*r20 + w[c*9+4]*r21 + w[c*9+5]*r22
                             + w[c*9+6]*r30 + w[c*9+7]*r31 + w[c*9+8]*r32;
                    if (c == 0) { a0 = ta; c0 = tb; }
                    else if (c == 1) { a1 = ta; c1 = tb; }
                    else { a2 = ta; c2 = tb; }
                }
                {
                    const float* p = s_c4 + j * 36 + i;
                    float r00 = p[0],   r01 = p[1],   r02 = p[2];
                    float r10 = p[36],  r11 = p[37],  r12 = p[38];
                    float r20 = p[72],  r21 = p[73],  r22 = p[74];
                    float r30 = p[108], r31 = p[109], r32 = p[110];
                    a3 = w[27]*r00 + w[28]*r01 + w[29]*r02
                       + w[30]*r10 + w[31]*r11 + w[32]*r12
                       + w[33]*r20 + w[34]*r21 + w[35]*r22;
                    c3 = w[27]*r10 + w[28]*r11 + w[29]*r12
                       + w[30]*r20 + w[31]*r21 + w[32]*r22
                       + w[33]*r30 + w[34]*r31 + w[35]*r32;
                }
                int gw = w0 + i - 1;
                bool wi = (unsigned)gw < (unsigned)Wdim;
                int gh = h0 + j - 1;
                bool i0 = wi && (unsigned)gh < (unsigned)Hdim;
                bool i1 = wi && (unsigned)(gh + 1) < (unsigned)Hdim;
                s_c5[j * 34 + i]       = i0 ? sigmoidf_(bia + (a0 + a1) + (a2 + a3)) : 0.0f;
                s_c5[(j + 1) * 34 + i] = i1 ? sigmoidf_(bia + (c0 + c1) + (c2 + c3)) : 0.0f;
            }
        }
        __syncthreads();

        // ====== conv3: [x,c4,c5] -> c6 + den + outf, 32x32, 2-row blocked ======
        {
            float w[45];
            #pragma unroll
            for (int k = 0; k < 45; k++) w[k] = s_w[63 + k];
            const float bia = s_b[2];

            #pragma unroll 1
            for (int item = tid; item < 16 * 32; item += NT) {
                int jp = item >> 5;
                int i  = item & 31;
                int j  = jp * 2;
                float a0 = 0, a1 = 0, a2 = 0, a3 = 0, a4 = 0;
                float c0 = 0, c1 = 0, c2 = 0, c3 = 0, c4v = 0;
                #pragma unroll
                for (int c = 0; c < 3; c++) {
                    const float* p = s_x + c * 1444 + (j + 2) * 38 + (i + 2);
                    float r00 = p[0],   r01 = p[1],   r02 = p[2];
                    float r10 = p[38],  r11 = p[39],  r12 = p[40];
                    float r20 = p[76],  r21 = p[77],  r22 = p[78];
                    float r30 = p[114], r31 = p[115], r32 = p[116];
                    float ta = w[c*9+0]*r00 + w[c*9+1]*r01 + w[c*9+2]*r02
                             + w[c*9+3]*r10 + w[c*9+4]*r11 + w[c*9+5]*r12
                             + w[c*9+6]*r20 + w[c*9+7]*r21 + w[c*9+8]*r22;
                    float tb = w[c*9+0]*r10 + w[c*9+1]*r11 + w[c*9+2]*r12
                             + w[c*9+3]*r20 + w[c*9+4]*r21 + w[c*9+5]*r22
                             + w[c*9+6]*r30 + w[c*9+7]*r31 + w[c*9+8]*r32;
                    if (c == 0) { a0 = ta; c0 = tb; }
                    else if (c == 1) { a1 = ta; c1 = tb; }
                    else { a2 = ta; c2 = tb; }
                }
                {
                    const float* p = s_c4 + (j + 1) * 36 + (i + 1);
                    float r00 = p[0],   r01 = p[1],   r02 = p[2];
                    float r10 = p[36],  r11 = p[37],  r12 = p[38];
                    float r20 = p[72],  r21 = p[73],  r22 = p[74];
                    float r30 = p[108], r31 = p[109], r32 = p[110];
                    a3 = w[27]*r00 + w[28]*r01 + w[29]*r02
                       + w[30]*r10 + w[31]*r11 + w[32]*r12
                       + w[33]*r20 + w[34]*r21 + w[35]*r22;
                    c3 = w[27]*r10 + w[28]*r11 + w[29]*r12
                       + w[30]*r20 + w[31]*r21 + w[32]*r22
                       + w[33]*r30 + w[34]*r31 + w[35]*r32;
                }
                {
                    const float* p = s_c5 + j * 34 + i;
                    float r00 = p[0],   r01 = p[1],   r02 = p[2];
                    float r10 = p[34],  r11 = p[35],  r12 = p[36];
                    float r20 = p[68],  r21 = p[69],  r22 = p[70];
                    float r30 = p[102], r31 = p[103], r32 = p[104];
                    a4 = w[36]*r00 + w[37]*r01 + w[38]*r02
                       + w[39]*r10 + w[40]*r11 + w[41]*r12
                       + w[42]*r20 + w[43]*r21 + w[44]*r22;
                    c4v = w[36]*r10 + w[37]*r11 + w[38]*r12
                        + w[39]*r20 + w[40]*r21 + w[41]*r22
                        + w[42]*r30 + w[43]*r31 + w[44]*r32;
                }

                #pragma unroll
                for (int r = 0; r < 2; r++) {
                    int jj = j + r;
                    float f5 = sigmoidf_(bia + (r == 0
                                 ? ((a0 + a1) + (a2 + a3) + a4)
                                 : ((c0 + c1) + (c2 + c3) + c4v)));
                    float f0 = s_x[0 * 1444 + (jj + 3) * 38 + (i + 3)];
                    float f1 = s_x[1 * 1444 + (jj + 3) * 38 + (i + 3)];
                    float f2 = s_x[2 * 1444 + (jj + 3) * 38 + (i + 3)];
                    float f3 = s_c4[(jj + 2) * 36 + (i + 2)];
                    float f4 = s_c5[(jj + 1) * 34 + (i + 1)];

                    int pix = (h0 + jj) * Wdim + (w0 + i);
                    float2* dp = (float2*)(den + (size_t)pix * 6);
                    dp[0] = make_float2(f0, f1);
                    dp[1] = make_float2(f2, f3);
                    dp[2] = make_float2(f4, f5);

                    float m0 = s_M[0]*f0 + s_M[1]*f1 + s_M[2]*f2
                             + s_M[3]*f3 + s_M[4]*f4 + s_M[5]*f5;
                    float m1 = s_M[6]*f0 + s_M[7]*f1 + s_M[8]*f2
                             + s_M[9]*f3 + s_M[10]*f4 + s_M[11]*f5;
                    float2* op = (float2*)outf + pix;
                    if (e == 0) {
                        *op = make_float2(s_B2[0] + m0, s_B2[1] + m1);
                    } else {
                        float2 prev = *op;  // same thread wrote it in e=0
                        *op = make_float2(prev.x - m0, prev.y - m1);
                    }
                }
            }
        }
    }
}

extern "C" void kernel_launch(void* const* d_in, const int* in_sizes, int n_in,
                              void* d_out, int out_size) {
    const float* x   = (const float*)d_in[0];
    const float* x2  = (const float*)d_in[1];
    const float* w1a = (const float*)d_in[2];
    const float* b1a = (const float*)d_in[3];
    const float* w2a = (const float*)d_in[4];
    const float* b2a = (const float*)d_in[5];
    const float* w3a = (const float*)d_in[6];
    const float* b3a = (const float*)d_in[7];
    const float* w1b = (const float*)d_in[8];
    const float* b1b = (const float*)d_in[9];
    const float* w2b = (const float*)d_in[10];
    const float* b2b = (const float*)d_in[11];
    const float* w3b = (const float*)d_in[12];
    const float* b3b = (const float*)d_in[13];
    const float* lw1 = (const float*)d_in[14];
    const float* lb1 = (const float*)d_in[15];
    const float* lw2 = (const float*)d_in[16];
    const float* lb2 = (const float*)d_in[17];

    float* outf = (float*)d_out;                       // [HW, 2]
    float* den1 = (float*)d_out + (size_t)2 * HWdim;   // [H, W, 6]
    float* den2 = (float*)d_out + (size_t)8 * HWdim;   // [H, W, 6]

    dim3 grid(Wdim / TS, Hdim / TS);
    unet_fused_kernel<<<grid, NT>>>(
        x, x2, w1a, b1a, w2a, b2a, w3a, b3a,
        w1b, b1b, w2b, b2b, w3b, b3b,
        lw1, lb1, lw2, lb2,
        outf, den1, den2);
}